// round 4
// baseline (speedup 1.0000x reference)
#include <cuda_runtime.h>
#include <cuda_bf16.h>
#include <cstdint>

// Problem constants
#define F_FIELDS 32
#define VOCAB    10000
#define D_EMB    496          // = 124 float4
#define D4       124
#define H_MLP    1024
#define B_BATCH  16384

#define MLP_BM      64                      // samples per MLP block
#define MLP_BLOCKS  (B_BATCH / MLP_BM)      // 256
#define FM_BLOCKS   B_BATCH                 // 1 sample per FM block (128 thr)

// ---------------------------------------------------------------------------
// Mixed kernel, single pass. out[] is pre-zeroed by a memset node; the MLP
// role and the FM role each contribute exactly one atomicAdd per sample.
// Two-float add is commutative -> result is order-independent (deterministic).
//
// Blocks [0, MLP_BLOCKS): FMA-bound MLP role (256 threads).
// Blocks [MLP_BLOCKS, MLP_BLOCKS+FM_BLOCKS): DRAM-bound FM gather role
// (uses 128 of 256 threads; small blocks smooth the tail wave).
// ---------------------------------------------------------------------------
__global__ void __launch_bounds__(256) mixed_kernel(
    const float* __restrict__ xv,
    const void*  __restrict__ xi_raw,
    const float* __restrict__ emb,
    const float* __restrict__ W1,
    const float* __restrict__ b1,
    const float* __restrict__ W2,
    const float* __restrict__ b2,
    float*       __restrict__ out)
{
    const int t = threadIdx.x;

    if (blockIdx.x < MLP_BLOCKS) {
        // ----------------- MLP role -----------------
        // 64 samples/block, 256 threads: thread owns sample s=t&63, hidden
        // range g=t>>6 (256 of 1024 units), float4 over j. W1/b1/W2 loads are
        // warp-uniform -> broadcast, L2-resident (W1 read 256x, not 16384x).
        __shared__ float xs[MLP_BM][33];
        __shared__ float accs[MLP_BM][4];

        const int b0 = blockIdx.x * MLP_BM;

        for (int i = t; i < MLP_BM * F_FIELDS; i += 256) {
            int s = i >> 5, f = i & 31;
            xs[s][f] = xv[(size_t)(b0 + s) * F_FIELDS + f];
        }
        __syncthreads();

        const int s = t & 63;
        const int g = t >> 6;

        float xr[F_FIELDS];
#pragma unroll
        for (int f = 0; f < F_FIELDS; ++f) xr[f] = xs[s][f];

        const float* w2h = W2 + D_EMB;   // rows [D, D+H) of W2
        float acc = 0.f;
        const int jbase = g * 256;

        for (int j = jbase; j < jbase + 256; j += 4) {
            float4 dot = *(const float4*)(b1 + j);
#pragma unroll
            for (int f = 0; f < F_FIELDS; ++f) {
                float4 w = *(const float4*)(W1 + f * H_MLP + j);
                dot.x = fmaf(xr[f], w.x, dot.x);
                dot.y = fmaf(xr[f], w.y, dot.y);
                dot.z = fmaf(xr[f], w.z, dot.z);
                dot.w = fmaf(xr[f], w.w, dot.w);
            }
            float4 wo = *(const float4*)(w2h + j);
            acc = fmaf(fmaxf(dot.x, 0.f), wo.x, acc);
            acc = fmaf(fmaxf(dot.y, 0.f), wo.y, acc);
            acc = fmaf(fmaxf(dot.z, 0.f), wo.z, acc);
            acc = fmaf(fmaxf(dot.w, 0.f), wo.w, acc);
        }

        accs[s][g] = acc;
        __syncthreads();
        if (t < MLP_BM)
            atomicAdd(out + b0 + t,
                      accs[t][0] + accs[t][1] + accs[t][2] + accs[t][3] + b2[0]);

    } else if (t < 128) {
        // ----------------- FM gather role -----------------
        // One sample per block. Thread t<124 owns dims [4t,4t+4): 32
        // independent float4 gathers, unroll 16 for deep load parallelism.
        __shared__ const float4* basep[F_FIELDS];
        __shared__ float vx[F_FIELDS];
        __shared__ int   is64_s;
        __shared__ float wsum[4];

        const int b = blockIdx.x - MLP_BLOCKS;

        // Inline index-dtype detection from the first 256B of xi: if the
        // buffer is int64 (values < 10000), every odd 32-bit word is 0.
        // For int32 random indices, P(32 odd words all zero) ~ 1e-128.
        if (t < 32) {
            int v = ((const int*)xi_raw)[2 * t + 1];
            unsigned nz = __ballot_sync(0xffffffff, v != 0);
            if (t == 0) is64_s = (nz == 0) ? 1 : 0;
        }
        __syncthreads();

        if (t < F_FIELDS) {
            int idx;
            if (is64_s) idx = (int)((const long long*)xi_raw)[(size_t)b * F_FIELDS + t];
            else        idx = ((const int*)xi_raw)[(size_t)b * F_FIELDS + t];
            basep[t] = (const float4*)emb + ((size_t)t * VOCAB + (size_t)idx) * D4;
            vx[t]    = xv[(size_t)b * F_FIELDS + t];
        }
        __syncthreads();

        float partial = 0.f;
        if (t < D4) {
            float4 s4 = make_float4(0.f, 0.f, 0.f, 0.f);
            float4 ss = make_float4(0.f, 0.f, 0.f, 0.f);
#pragma unroll 16
            for (int f = 0; f < F_FIELDS; ++f) {
                const float  v = vx[f];
                const float4 r = __ldg(basep[f] + t);
                float ex = r.x * v, ey = r.y * v, ez = r.z * v, ew = r.w * v;
                s4.x += ex;  s4.y += ey;  s4.z += ez;  s4.w += ew;
                ss.x = fmaf(ex, ex, ss.x);
                ss.y = fmaf(ey, ey, ss.y);
                ss.z = fmaf(ez, ez, ss.z);
                ss.w = fmaf(ew, ew, ss.w);
            }
            const float4 w = ((const float4*)W2)[t];  // first D rows of W2
            partial = 0.5f * ((s4.x * s4.x - ss.x) * w.x +
                              (s4.y * s4.y - ss.y) * w.y +
                              (s4.z * s4.z - ss.z) * w.z +
                              (s4.w * s4.w - ss.w) * w.w);
        }

        // reduce across the 128 active threads (4 warps)
#pragma unroll
        for (int o = 16; o > 0; o >>= 1)
            partial += __shfl_down_sync(0xffffffff, partial, o);

        if ((t & 31) == 0) wsum[t >> 5] = partial;
        __syncthreads();
        if (t == 0)
            atomicAdd(out + b, wsum[0] + wsum[1] + wsum[2] + wsum[3]);
    }
}

// ---------------------------------------------------------------------------
extern "C" void kernel_launch(void* const* d_in, const int* in_sizes, int n_in,
                              void* d_out, int out_size)
{
    const float* xv  = (const float*)d_in[0];
    const void*  xi  = d_in[1];
    const float* emb = (const float*)d_in[2];
    const float* W1  = (const float*)d_in[3];
    const float* b1  = (const float*)d_in[4];
    const float* W2  = (const float*)d_in[5];
    const float* b2  = (const float*)d_in[6];
    float* out = (float*)d_out;

    // Zero the accumulator; both roles atomicAdd exactly once per element.
    // Async memset on the capture stream -> a memset node in the graph
    // (no allocation, no synchronization).
    cudaMemsetAsync(out, 0, (size_t)out_size * sizeof(float), 0);

    mixed_kernel<<<MLP_BLOCKS + FM_BLOCKS, 256>>>(xv, xi, emb, W1, b1, W2, b2, out);
}